// round 16
// baseline (speedup 1.0000x reference)
#include <cuda_runtime.h>
#include <cuda_fp16.h>
#include <cstdint>

#define HIDDEN   1024
#define EMB      512
#define NUM_OPS  8
#define BATCH    16384

#define BM 128
#define BN 128
#define BK 32
#define PIPE 4
#define NTHREADS 256
#define MAX_TILES 136        // sum_e ceil(c_e/BM) <= 128 + 7, padded

// smem row stride: 32 halves + 8 pad = 40 halves = 80 bytes (16B-aligned)
// LDSM 8-row phase: row i starts at word-bank (20*i)%32 -> 8 rows x 4 words tile all 32 banks
#define ROW_BYTES 80
#define A_STAGE_BYTES (BM * ROW_BYTES)     // 10240
#define B_STAGE_BYTES (BN * ROW_BYTES)     // 10240 (B stored [n][k])
#define STAGE_BYTES (A_STAGE_BYTES + B_STAGE_BYTES)
#define DYN_SMEM (PIPE * STAGE_BYTES)      // 81920

// ---- scratch (static device globals: no allocations allowed) ----
__device__ int    g_offsets[NUM_OPS + 1];
__device__ int    g_ntiles;
__device__ int    g_tile_e[MAX_TILES];
__device__ int    g_tile_row0[MAX_TILES];
__device__ int    g_perm[BATCH];
__device__ __half g_xh[(size_t)BATCH * HIDDEN];            // fp16 x
__device__ __half g_embh[NUM_OPS * EMB];                   // fp16 op_emb
__device__ __half g_w1t[(size_t)NUM_OPS * HIDDEN * 1536];  // fp16 W1^T [e][n][k]
__device__ __half g_w2t[(size_t)NUM_OPS * HIDDEN * 1024];  // fp16 W2^T [e][n][k]
__device__ __half g_h[(size_t)BATCH * HIDDEN];             // layer-1 out (sorted, fp16)

// ---- helpers ----
__device__ __forceinline__ uint32_t smem_u32(const void* p) {
    uint32_t a;
    asm("{ .reg .u64 t; cvta.to.shared.u64 t, %1; cvt.u32.u64 %0, t; }" : "=r"(a) : "l"(p));
    return a;
}
__device__ __forceinline__ void cp16(uint32_t s, const void* g) {
    asm volatile("cp.async.cg.shared.global [%0], [%1], 16;" :: "r"(s), "l"(g));
}
__device__ __forceinline__ void cp_commit() { asm volatile("cp.async.commit_group;"); }
template <int N> __device__ __forceinline__ void cp_wait() {
    asm volatile("cp.async.wait_group %0;" :: "n"(N));
}
__device__ __forceinline__ void ldsm4(uint32_t& d0, uint32_t& d1, uint32_t& d2, uint32_t& d3,
                                      uint32_t addr) {
    asm volatile("ldmatrix.sync.aligned.m8n8.x4.shared.b16 {%0,%1,%2,%3}, [%4];"
                 : "=r"(d0), "=r"(d1), "=r"(d2), "=r"(d3) : "r"(addr));
}
__device__ __forceinline__ void mma_f16(float c[4],
                                        uint32_t a0, uint32_t a1, uint32_t a2, uint32_t a3,
                                        uint32_t b0, uint32_t b1) {
    asm volatile(
        "mma.sync.aligned.m16n8k16.row.col.f32.f16.f16.f32 "
        "{%0,%1,%2,%3}, {%4,%5,%6,%7}, {%8,%9}, {%0,%1,%2,%3};"
        : "+f"(c[0]), "+f"(c[1]), "+f"(c[2]), "+f"(c[3])
        : "r"(a0), "r"(a1), "r"(a2), "r"(a3), "r"(b0), "r"(b1));
}

// ---- fused routing: hist + scan + tile table + scatter, one CTA of 32 warps ----
__global__ __launch_bounds__(1024) void route_kernel(const int* __restrict__ ops) {
    __shared__ int s_cnt[NUM_OPS];
    __shared__ int s_cur[NUM_OPS];
    const int tid  = threadIdx.x;
    const int lane = tid & 31;
    const int w    = tid >> 5;            // 0..31
    if (tid < NUM_OPS) s_cnt[tid] = 0;
    __syncthreads();

    // each warp owns 512 consecutive tokens: 16 rounds of 32
    int myop[16];
    const int base = w * 512 + lane;
#pragma unroll
    for (int r = 0; r < 16; ++r) myop[r] = ops[base + r * 32];

    // phase A: per-warp histogram via ballots, leader accumulates
    int cnt[NUM_OPS];
#pragma unroll
    for (int e = 0; e < NUM_OPS; ++e) cnt[e] = 0;
#pragma unroll
    for (int r = 0; r < 16; ++r) {
#pragma unroll
        for (int e = 0; e < NUM_OPS; ++e) {
            unsigned m = __ballot_sync(0xffffffffu, myop[r] == e);
            cnt[e] += __popc(m);
        }
    }
    if (lane == 0)
#pragma unroll
        for (int e = 0; e < NUM_OPS; ++e) atomicAdd(&s_cnt[e], cnt[e]);
    __syncthreads();

    // scan + tile table (thread 0)
    if (tid == 0) {
        int acc = 0, nt = 0;
        for (int e = 0; e < NUM_OPS; ++e) {
            g_offsets[e] = acc;
            s_cur[e] = acc;
            const int c = s_cnt[e];
            for (int j = 0; j < c; j += BM) {
                g_tile_e[nt] = e;
                g_tile_row0[nt] = acc + j;
                ++nt;
            }
            acc += c;
        }
        g_offsets[NUM_OPS] = acc;
        g_ntiles = nt;
    }
    __syncthreads();

    // phase B: scatter with smem cursors (warp-aggregated atomics)
#pragma unroll
    for (int r = 0; r < 16; ++r) {
        const int tok = base + r * 32;
        const int op = myop[r];
#pragma unroll
        for (int e = 0; e < NUM_OPS; ++e) {
            unsigned m = __ballot_sync(0xffffffffu, op == e);
            if (!m) continue;
            const int leader = __ffs(m) - 1;
            int b = 0;
            if (lane == leader) b = atomicAdd(&s_cur[e], __popc(m));
            b = __shfl_sync(0xffffffffu, b, leader);
            if (op == e) g_perm[b + __popc(m & ((1u << lane) - 1u))] = tok;
        }
    }
}

// ---- fused fp16 convert of x and op_emb ----
__global__ void cvt_all_kernel(const float4* __restrict__ x, const float4* __restrict__ emb,
                               uint2* __restrict__ xh, uint2* __restrict__ eh) {
    const int NX = BATCH * HIDDEN / 4;
    const int NE = NUM_OPS * EMB / 4;
    int i = blockIdx.x * blockDim.x + threadIdx.x;
    const float4* src;
    uint2* dst;
    if (i < NX) { src = x + i; dst = xh + i; }
    else if (i < NX + NE) { src = emb + (i - NX); dst = eh + (i - NX); }
    else return;
    float4 v = *src;
    __half2 h01 = __floats2half2_rn(v.x, v.y);
    __half2 h23 = __floats2half2_rn(v.z, v.w);
    uint2 o;
    o.x = *(uint32_t*)&h01;
    o.y = *(uint32_t*)&h23;
    *dst = o;
}

// ---- fused W1/W2 [e][k][n] fp32 -> [e][n][k] fp16 (32x32 tiles) ----
__global__ void transpose_cvt2_kernel(const float* __restrict__ W1, const float* __restrict__ W2,
                                      __half* __restrict__ Wt1, __half* __restrict__ Wt2) {
    __shared__ float t[32][33];
    const bool isW1 = blockIdx.z < NUM_OPS;
    const int e = blockIdx.z & (NUM_OPS - 1);
    const int K = isW1 ? 1536 : 1024;
    const int n0 = blockIdx.x * 32, k0 = blockIdx.y * 32;
    if (k0 >= K) return;
    const float* Wb = (isW1 ? W1 : W2) + (size_t)e * K * HIDDEN;
    __half* Wtb = (isW1 ? Wt1 : Wt2) + (size_t)e * HIDDEN * K;
    const int tid = threadIdx.x;   // 256
#pragma unroll
    for (int i = 0; i < 4; ++i) {
        int idx = tid + 256 * i;
        int n = idx & 31, k = idx >> 5;
        t[k][n] = Wb[(size_t)(k0 + k) * HIDDEN + n0 + n];
    }
    __syncthreads();
#pragma unroll
    for (int i = 0; i < 2; ++i) {
        int idx = tid + 256 * i;
        int nl = idx >> 4, p = idx & 15;
        __half2 h = __floats2half2_rn(t[2 * p][nl], t[2 * p + 1][nl]);
        *(__half2*)(Wtb + (size_t)(n0 + nl) * K + k0 + 2 * p) = h;
    }
}

// ---- grouped GEMM, fp16 mma m16n8k16 (fp32 accum), 4-stage cp.async, ldmatrix ----
// Identical inner loop to the 716us R12 kernel; grid compacted via tile table.
template <int LAYER>
__global__ __launch_bounds__(NTHREADS, 2) void gemm_tc(
    const float* __restrict__ bias, float* __restrict__ out)
{
    constexpr int K  = (LAYER == 1) ? 1536 : 1024;
    constexpr int KT = K / BK;

    if ((int)blockIdx.y >= g_ntiles) return;
    const int e = g_tile_e[blockIdx.y];
    const int row0 = g_tile_row0[blockIdx.y];
    const int seg_hi = g_offsets[e + 1];
    const int n0 = blockIdx.x * BN;

    extern __shared__ char dyn[];
    const uint32_t sbase = smem_u32(dyn);

    const int tid  = threadIdx.x;
    const int lane = tid & 31;
    const int warp = tid >> 5;
    const int wm = (warp & 1) * 64;    // 2 warps along M
    const int wn = (warp >> 1) * 32;   // 4 warps along N
    const int r  = lane >> 2;
    const int cc = lane & 3;

    // A loader: row = tid>>1 (0..127), two 16B chunks (16 halves) per thread
    const int arow_loc = tid >> 1;
    const int ac0 = (tid & 1) * 2;
    int arow = row0 + arow_loc;
    if (arow > seg_hi - 1) arow = seg_hi - 1;      // clamp; masked at store
    const __half* Abase;
    if (LAYER == 1) Abase = g_xh + (size_t)g_perm[arow] * HIDDEN;
    else            Abase = g_h + (size_t)arow * HIDDEN;
    const __half* Ebase = g_embh + e * EMB;
    const uint32_t a_soff = (uint32_t)(arow_loc * ROW_BYTES + ac0 * 16);

    // B loader: n-row = tid>>1, two 16B chunks per thread; B stored [n][k] K-major
    const __half* Wt = (LAYER == 1) ? g_w1t : g_w2t;
    const __half* Bbase = Wt + ((size_t)e * HIDDEN + n0 + arow_loc) * K + ac0 * 8;
    const uint32_t b_soff = (uint32_t)(A_STAGE_BYTES + arow_loc * ROW_BYTES + ac0 * 16);

    auto load_stage = [&](int s) {
        const int kb = s * BK;
        const uint32_t st = sbase + (uint32_t)((s % PIPE) * STAGE_BYTES);
        const bool emb_stage = (LAYER == 1) && (kb >= HIDDEN);
        const __half* asrc = emb_stage ? (Ebase + (kb - HIDDEN) + ac0 * 8)
                                       : (Abase + kb + ac0 * 8);
#pragma unroll
        for (int j = 0; j < 2; ++j) cp16(st + a_soff + j * 16u, asrc + j * 8);
        const __half* bsrc = Bbase + kb;
#pragma unroll
        for (int j = 0; j < 2; ++j) cp16(st + b_soff + j * 16u, bsrc + j * 8);
    };

    // ldmatrix per-thread base offsets (within a stage)
    const uint32_t a_lds = (uint32_t)((wm + (lane & 15)) * ROW_BYTES + ((lane >> 4) & 1) * 16);
    const uint32_t b_lds = (uint32_t)(A_STAGE_BYTES +
                                      (wn + ((lane >> 4) & 1) * 8 + (lane & 7)) * ROW_BYTES +
                                      ((lane >> 3) & 1) * 16);

    float c[4][4][4];
#pragma unroll
    for (int mt = 0; mt < 4; ++mt)
#pragma unroll
        for (int nt = 0; nt < 4; ++nt)
#pragma unroll
            for (int i = 0; i < 4; ++i) c[mt][nt][i] = 0.f;

    auto compute = [&](int buf) {
        const uint32_t sb = sbase + (uint32_t)buf * STAGE_BYTES;
#pragma unroll
        for (int ks = 0; ks < 2; ++ks) {           // 2 x K=16 slices cover BK=32
            const uint32_t ko = (uint32_t)(ks * 32);
            uint32_t af[4][4];
            uint32_t bf[4][2];
#pragma unroll
            for (int mt = 0; mt < 4; ++mt)
                ldsm4(af[mt][0], af[mt][1], af[mt][2], af[mt][3],
                      sb + a_lds + (uint32_t)(mt * 16 * ROW_BYTES) + ko);
#pragma unroll
            for (int p = 0; p < 2; ++p)
                ldsm4(bf[2 * p][0], bf[2 * p][1], bf[2 * p + 1][0], bf[2 * p + 1][1],
                      sb + b_lds + (uint32_t)(p * 16 * ROW_BYTES) + ko);
#pragma unroll
            for (int mt = 0; mt < 4; ++mt)
#pragma unroll
                for (int nt = 0; nt < 4; ++nt)
                    mma_f16(c[mt][nt], af[mt][0], af[mt][1], af[mt][2], af[mt][3],
                            bf[nt][0], bf[nt][1]);
        }
    };

    // prologue: 3 stages in flight
    load_stage(0); cp_commit();
    load_stage(1); cp_commit();
    load_stage(2); cp_commit();

    for (int kt = 0; kt < KT; ++kt) {
        cp_wait<2>();                 // stage kt resident; kt+1, kt+2 still in flight
        __syncthreads();              // all warps see stage kt; all done reading buf (kt+3)%4
        if (kt + 3 < KT) load_stage(kt + 3);
        cp_commit();                  // uniform (possibly empty) commit keeps group counts fixed
        compute(kt % PIPE);
    }

    // epilogue: bias + relu; layer1 -> fp16 g_h, layer2 -> fp32 scatter
    const float* brow = bias + e * HIDDEN;
#pragma unroll
    for (int mt = 0; mt < 4; ++mt) {
        const int rbase = row0 + wm + mt * 16 + r;
#pragma unroll
        for (int half = 0; half < 2; ++half) {
            const int row = rbase + half * 8;
            if (row >= seg_hi) continue;
#pragma unroll
            for (int nt = 0; nt < 4; ++nt) {
                const int col = n0 + wn + nt * 8 + 2 * cc;
                float v0 = c[mt][nt][half * 2 + 0] + __ldg(brow + col);
                float v1 = c[mt][nt][half * 2 + 1] + __ldg(brow + col + 1);
                v0 = v0 > 0.f ? v0 : 0.f;
                v1 = v1 > 0.f ? v1 : 0.f;
                if (LAYER == 1) {
                    __half2 h = __floats2half2_rn(v0, v1);
                    *(__half2*)(g_h + (size_t)row * HIDDEN + col) = h;
                } else {
                    *(float2*)(out + (size_t)g_perm[row] * HIDDEN + col) = make_float2(v0, v1);
                }
            }
        }
    }
}

extern "C" void kernel_launch(void* const* d_in, const int* in_sizes, int n_in,
                              void* d_out, int out_size) {
    const float* x      = (const float*)d_in[0];
    const int*   ops    = (const int*)  d_in[1];
    const float* op_emb = (const float*)d_in[2];
    const float* W1     = (const float*)d_in[3];
    const float* b1     = (const float*)d_in[4];
    const float* W2     = (const float*)d_in[5];
    const float* b2     = (const float*)d_in[6];
    float* out = (float*)d_out;

    cudaFuncSetAttribute(gemm_tc<1>, cudaFuncAttributeMaxDynamicSharedMemorySize, DYN_SMEM);
    cudaFuncSetAttribute(gemm_tc<2>, cudaFuncAttributeMaxDynamicSharedMemorySize, DYN_SMEM);

    // routing + tile table (one kernel)
    route_kernel<<<1, 1024>>>(ops);

    // fp16 conversion (x + emb fused) and weight transpose (W1 + W2 fused)
    {
        __half* xh;  cudaGetSymbolAddress((void**)&xh,  g_xh);
        __half* eh;  cudaGetSymbolAddress((void**)&eh,  g_embh);
        __half* w1t; cudaGetSymbolAddress((void**)&w1t, g_w1t);
        __half* w2t; cudaGetSymbolAddress((void**)&w2t, g_w2t);
        const int ntot = (BATCH * HIDDEN + NUM_OPS * EMB) / 4;
        cvt_all_kernel<<<(ntot + 255) / 256, 256>>>((const float4*)x, (const float4*)op_emb,
                                                    (uint2*)xh, (uint2*)eh);
        transpose_cvt2_kernel<<<dim3(HIDDEN / 32, 1536 / 32, 2 * NUM_OPS), 256>>>(W1, W2, w1t, w2t);
    }

    dim3 grid(HIDDEN / BN, MAX_TILES - 1, 1);   // 8 x 135; excess tiles guarded by g_ntiles
    gemm_tc<1><<<grid, NTHREADS, DYN_SMEM>>>(b1, nullptr);
    gemm_tc<2><<<grid, NTHREADS, DYN_SMEM>>>(b2, out);
}

// round 17
// speedup vs baseline: 1.4349x; 1.4349x over previous
#include <cuda_runtime.h>
#include <cuda_fp16.h>
#include <cstdint>

#define HIDDEN   1024
#define EMB      512
#define NUM_OPS  8
#define BATCH    16384

#define BM 128
#define BN 128
#define BK 32
#define PIPE 4
#define NTHREADS 256

// smem row stride: 32 halves + 8 pad = 40 halves = 80 bytes (16B-aligned)
// LDSM 8-row phase: row i starts at word-bank (20*i)%32 -> 8 rows x 4 words tile all 32 banks
#define ROW_BYTES 80
#define A_STAGE_BYTES (BM * ROW_BYTES)     // 10240
#define B_STAGE_BYTES (BN * ROW_BYTES)     // 10240 (B stored [n][k])
#define STAGE_BYTES (A_STAGE_BYTES + B_STAGE_BYTES)
#define DYN_SMEM (PIPE * STAGE_BYTES)      // 81920 -> 2 CTAs/SM

// ---- scratch (static device globals: no allocations allowed) ----
__device__ int    g_counts[NUM_OPS];
__device__ int    g_cursor[NUM_OPS];
__device__ int    g_offsets[NUM_OPS + 1];
__device__ int    g_perm[BATCH];
__device__ __half g_xh[(size_t)BATCH * HIDDEN];            // fp16 x
__device__ __half g_embh[NUM_OPS * EMB];                   // fp16 op_emb
__device__ __half g_w1t[(size_t)NUM_OPS * HIDDEN * 1536];  // fp16 W1^T [e][n][k]
__device__ __half g_w2t[(size_t)NUM_OPS * HIDDEN * 1024];  // fp16 W2^T [e][n][k]
__device__ __half g_h[(size_t)BATCH * HIDDEN];             // layer-1 out (sorted, fp16)

// ---- helpers ----
__device__ __forceinline__ uint32_t smem_u32(const void* p) {
    uint32_t a;
    asm("{ .reg .u64 t; cvta.to.shared.u64 t, %1; cvt.u32.u64 %0, t; }" : "=r"(a) : "l"(p));
    return a;
}
__device__ __forceinline__ void cp16(uint32_t s, const void* g) {
    asm volatile("cp.async.cg.shared.global [%0], [%1], 16;" :: "r"(s), "l"(g));
}
__device__ __forceinline__ void cp_commit() { asm volatile("cp.async.commit_group;"); }
template <int N> __device__ __forceinline__ void cp_wait() {
    asm volatile("cp.async.wait_group %0;" :: "n"(N));
}
__device__ __forceinline__ void ldsm4(uint32_t& d0, uint32_t& d1, uint32_t& d2, uint32_t& d3,
                                      uint32_t addr) {
    asm volatile("ldmatrix.sync.aligned.m8n8.x4.shared.b16 {%0,%1,%2,%3}, [%4];"
                 : "=r"(d0), "=r"(d1), "=r"(d2), "=r"(d3) : "r"(addr));
}
__device__ __forceinline__ void mma_f16(float c[4],
                                        uint32_t a0, uint32_t a1, uint32_t a2, uint32_t a3,
                                        uint32_t b0, uint32_t b1) {
    asm volatile(
        "mma.sync.aligned.m16n8k16.row.col.f32.f16.f16.f32 "
        "{%0,%1,%2,%3}, {%4,%5,%6,%7}, {%8,%9}, {%0,%1,%2,%3};"
        : "+f"(c[0]), "+f"(c[1]), "+f"(c[2]), "+f"(c[3])
        : "r"(a0), "r"(a1), "r"(a2), "r"(a3), "r"(b0), "r"(b1));
}

// ---- routing (proven-cheap 4-kernel chain from the 716us run) ----
__global__ void init_kernel() { if (threadIdx.x < NUM_OPS) g_counts[threadIdx.x] = 0; }
__global__ void hist_kernel(const int* __restrict__ ops) {
    int i = blockIdx.x * blockDim.x + threadIdx.x;
    if (i < BATCH) atomicAdd(&g_counts[ops[i]], 1);
}
__global__ void scan_kernel() {
    int acc = 0;
    for (int e = 0; e < NUM_OPS; ++e) { g_offsets[e] = acc; g_cursor[e] = acc; acc += g_counts[e]; }
    g_offsets[NUM_OPS] = acc;
}
__global__ void scatter_kernel(const int* __restrict__ ops) {
    int i = blockIdx.x * blockDim.x + threadIdx.x;
    if (i < BATCH) { int pos = atomicAdd(&g_cursor[ops[i]], 1); g_perm[pos] = i; }
}

// ---- fused fp16 convert of x and op_emb ----
__global__ void cvt_all_kernel(const float4* __restrict__ x, const float4* __restrict__ emb,
                               uint2* __restrict__ xh, uint2* __restrict__ eh) {
    const int NX = BATCH * HIDDEN / 4;
    const int NE = NUM_OPS * EMB / 4;
    int i = blockIdx.x * blockDim.x + threadIdx.x;
    const float4* src;
    uint2* dst;
    if (i < NX) { src = x + i; dst = xh + i; }
    else if (i < NX + NE) { src = emb + (i - NX); dst = eh + (i - NX); }
    else return;
    float4 v = *src;
    __half2 h01 = __floats2half2_rn(v.x, v.y);
    __half2 h23 = __floats2half2_rn(v.z, v.w);
    uint2 o;
    o.x = *(uint32_t*)&h01;
    o.y = *(uint32_t*)&h23;
    *dst = o;
}

// ---- fused W1/W2 [e][k][n] fp32 -> [e][n][k] fp16 (32x32 tiles) ----
__global__ void transpose_cvt2_kernel(const float* __restrict__ W1, const float* __restrict__ W2,
                                      __half* __restrict__ Wt1, __half* __restrict__ Wt2) {
    __shared__ float t[32][33];
    const bool isW1 = blockIdx.z < NUM_OPS;
    const int e = blockIdx.z & (NUM_OPS - 1);
    const int K = isW1 ? 1536 : 1024;
    const int n0 = blockIdx.x * 32, k0 = blockIdx.y * 32;
    if (k0 >= K) return;
    const float* Wb = (isW1 ? W1 : W2) + (size_t)e * K * HIDDEN;
    __half* Wtb = (isW1 ? Wt1 : Wt2) + (size_t)e * HIDDEN * K;
    const int tid = threadIdx.x;   // 256
#pragma unroll
    for (int i = 0; i < 4; ++i) {
        int idx = tid + 256 * i;
        int n = idx & 31, k = idx >> 5;
        t[k][n] = Wb[(size_t)(k0 + k) * HIDDEN + n0 + n];
    }
    __syncthreads();
#pragma unroll
    for (int i = 0; i < 2; ++i) {
        int idx = tid + 256 * i;
        int nl = idx >> 4, p = idx & 15;
        __half2 h = __floats2half2_rn(t[2 * p][nl], t[2 * p + 1][nl]);
        *(__half2*)(Wtb + (size_t)(n0 + nl) * K + k0 + 2 * p) = h;
    }
}

// ---- grouped GEMM, fp16 mma m16n8k16 (fp32 accum), 4-stage cp.async, ldmatrix ----
// Inner loop bit-identical to the 716us R12 kernel; z-expert grid as in R12.
template <int LAYER>
__global__ __launch_bounds__(NTHREADS, 2) void gemm_tc(
    const float* __restrict__ bias, float* __restrict__ out)
{
    constexpr int K  = (LAYER == 1) ? 1536 : 1024;
    constexpr int KT = K / BK;

    const int e = blockIdx.z;
    const int seg_lo = g_offsets[e];
    const int seg_hi = g_offsets[e + 1];
    const int row0 = seg_lo + blockIdx.y * BM;
    if (row0 >= seg_hi) return;
    const int n0 = blockIdx.x * BN;

    extern __shared__ char dyn[];
    const uint32_t sbase = smem_u32(dyn);

    const int tid  = threadIdx.x;
    const int lane = tid & 31;
    const int warp = tid >> 5;
    const int wm = (warp & 1) * 64;    // 2 warps along M
    const int wn = (warp >> 1) * 32;   // 4 warps along N
    const int r  = lane >> 2;
    const int cc = lane & 3;

    // A loader: row = tid>>1 (0..127), two 16B chunks (16 halves) per thread
    const int arow_loc = tid >> 1;
    const int ac0 = (tid & 1) * 2;
    int arow = row0 + arow_loc;
    if (arow > seg_hi - 1) arow = seg_hi - 1;      // clamp; masked at store
    const __half* Abase;
    if (LAYER == 1) Abase = g_xh + (size_t)g_perm[arow] * HIDDEN;
    else            Abase = g_h + (size_t)arow * HIDDEN;
    const __half* Ebase = g_embh + e * EMB;
    const uint32_t a_soff = (uint32_t)(arow_loc * ROW_BYTES + ac0 * 16);

    // B loader: n-row = tid>>1, two 16B chunks per thread; B stored [n][k] K-major
    const __half* Wt = (LAYER == 1) ? g_w1t : g_w2t;
    const __half* Bbase = Wt + ((size_t)e * HIDDEN + n0 + arow_loc) * K + ac0 * 8;
    const uint32_t b_soff = (uint32_t)(A_STAGE_BYTES + arow_loc * ROW_BYTES + ac0 * 16);

    auto load_stage = [&](int s) {
        const int kb = s * BK;
        const uint32_t st = sbase + (uint32_t)((s % PIPE) * STAGE_BYTES);
        const bool emb_stage = (LAYER == 1) && (kb >= HIDDEN);
        const __half* asrc = emb_stage ? (Ebase + (kb - HIDDEN) + ac0 * 8)
                                       : (Abase + kb + ac0 * 8);
#pragma unroll
        for (int j = 0; j < 2; ++j) cp16(st + a_soff + j * 16u, asrc + j * 8);
        const __half* bsrc = Bbase + kb;
#pragma unroll
        for (int j = 0; j < 2; ++j) cp16(st + b_soff + j * 16u, bsrc + j * 8);
    };

    // bias prefetch: 8 values per thread, loaded before the main loop
    const float* brow = bias + e * HIDDEN;
    float bv[4][2];
#pragma unroll
    for (int nt = 0; nt < 4; ++nt) {
        const int col = n0 + wn + nt * 8 + 2 * cc;
        bv[nt][0] = __ldg(brow + col);
        bv[nt][1] = __ldg(brow + col + 1);
    }

    // ldmatrix per-thread base offsets (within a stage)
    const uint32_t a_lds = (uint32_t)((wm + (lane & 15)) * ROW_BYTES + ((lane >> 4) & 1) * 16);
    const uint32_t b_lds = (uint32_t)(A_STAGE_BYTES +
                                      (wn + ((lane >> 4) & 1) * 8 + (lane & 7)) * ROW_BYTES +
                                      ((lane >> 3) & 1) * 16);

    float c[4][4][4];
#pragma unroll
    for (int mt = 0; mt < 4; ++mt)
#pragma unroll
        for (int nt = 0; nt < 4; ++nt)
#pragma unroll
            for (int i = 0; i < 4; ++i) c[mt][nt][i] = 0.f;

    auto compute = [&](int buf) {
        const uint32_t sb = sbase + (uint32_t)buf * STAGE_BYTES;
#pragma unroll
        for (int ks = 0; ks < 2; ++ks) {           // 2 x K=16 slices cover BK=32
            const uint32_t ko = (uint32_t)(ks * 32);
            uint32_t af[4][4];
            uint32_t bf[4][2];
#pragma unroll
            for (int mt = 0; mt < 4; ++mt)
                ldsm4(af[mt][0], af[mt][1], af[mt][2], af[mt][3],
                      sb + a_lds + (uint32_t)(mt * 16 * ROW_BYTES) + ko);
#pragma unroll
            for (int p = 0; p < 2; ++p)
                ldsm4(bf[2 * p][0], bf[2 * p][1], bf[2 * p + 1][0], bf[2 * p + 1][1],
                      sb + b_lds + (uint32_t)(p * 16 * ROW_BYTES) + ko);
#pragma unroll
            for (int mt = 0; mt < 4; ++mt)
#pragma unroll
                for (int nt = 0; nt < 4; ++nt)
                    mma_f16(c[mt][nt], af[mt][0], af[mt][1], af[mt][2], af[mt][3],
                            bf[nt][0], bf[nt][1]);
        }
    };

    // prologue: 3 stages in flight
    load_stage(0); cp_commit();
    load_stage(1); cp_commit();
    load_stage(2); cp_commit();

    for (int kt = 0; kt < KT; ++kt) {
        cp_wait<2>();                 // stage kt resident; kt+1, kt+2 still in flight
        __syncthreads();              // all warps see stage kt; all done reading buf (kt+3)%4
        if (kt + 3 < KT) load_stage(kt + 3);
        cp_commit();                  // uniform (possibly empty) commit keeps group counts fixed
        compute(kt % PIPE);
    }

    // epilogue: bias + relu; layer1 -> fp16 g_h, layer2 -> fp32 scatter
#pragma unroll
    for (int mt = 0; mt < 4; ++mt) {
        const int rbase = row0 + wm + mt * 16 + r;
#pragma unroll
        for (int half = 0; half < 2; ++half) {
            const int row = rbase + half * 8;
            if (row >= seg_hi) continue;
#pragma unroll
            for (int nt = 0; nt < 4; ++nt) {
                const int col = n0 + wn + nt * 8 + 2 * cc;
                float v0 = c[mt][nt][half * 2 + 0] + bv[nt][0];
                float v1 = c[mt][nt][half * 2 + 1] + bv[nt][1];
                v0 = v0 > 0.f ? v0 : 0.f;
                v1 = v1 > 0.f ? v1 : 0.f;
                if (LAYER == 1) {
                    __half2 h = __floats2half2_rn(v0, v1);
                    *(__half2*)(g_h + (size_t)row * HIDDEN + col) = h;
                } else {
                    *(float2*)(out + (size_t)g_perm[row] * HIDDEN + col) = make_float2(v0, v1);
                }
            }
        }
    }
}

extern "C" void kernel_launch(void* const* d_in, const int* in_sizes, int n_in,
                              void* d_out, int out_size) {
    const float* x      = (const float*)d_in[0];
    const int*   ops    = (const int*)  d_in[1];
    const float* op_emb = (const float*)d_in[2];
    const float* W1     = (const float*)d_in[3];
    const float* b1     = (const float*)d_in[4];
    const float* W2     = (const float*)d_in[5];
    const float* b2     = (const float*)d_in[6];
    float* out = (float*)d_out;

    cudaFuncSetAttribute(gemm_tc<1>, cudaFuncAttributeMaxDynamicSharedMemorySize, DYN_SMEM);
    cudaFuncSetAttribute(gemm_tc<2>, cudaFuncAttributeMaxDynamicSharedMemorySize, DYN_SMEM);

    // routing (R12 configuration)
    init_kernel<<<1, 32>>>();
    hist_kernel<<<BATCH / 256, 256>>>(ops);
    scan_kernel<<<1, 1>>>();
    scatter_kernel<<<BATCH / 256, 256>>>(ops);

    // fp16 conversion (x + emb fused) and weight transpose (W1 + W2 fused)
    {
        __half* xh;  cudaGetSymbolAddress((void**)&xh,  g_xh);
        __half* eh;  cudaGetSymbolAddress((void**)&eh,  g_embh);
        __half* w1t; cudaGetSymbolAddress((void**)&w1t, g_w1t);
        __half* w2t; cudaGetSymbolAddress((void**)&w2t, g_w2t);
        const int ntot = (BATCH * HIDDEN + NUM_OPS * EMB) / 4;
        cvt_all_kernel<<<(ntot + 255) / 256, 256>>>((const float4*)x, (const float4*)op_emb,
                                                    (uint2*)xh, (uint2*)eh);
        transpose_cvt2_kernel<<<dim3(HIDDEN / 32, 1536 / 32, 2 * NUM_OPS), 256>>>(W1, W2, w1t, w2t);
    }

    // R12 z-expert grid (empty tiles early-return)
    dim3 grid(HIDDEN / BN, BATCH / BM, NUM_OPS);
    gemm_tc<1><<<grid, NTHREADS, DYN_SMEM>>>(b1, nullptr);
    gemm_tc<2><<<grid, NTHREADS, DYN_SMEM>>>(b2, out);
}